// round 13
// baseline (speedup 1.0000x reference)
#include <cuda_runtime.h>
#include <math.h>
#include <stdint.h>

// Problem constants
#define BSZ 4
#define NSEQ 2048
#define DMODEL 256
#define HH 8
#define DHD 32
#define RR 64
#define KSP 32
#define MROWS (BSZ * NSEQ)   // 8192

// ---------------------------------------------------------------------------
// Scratch arena (float offsets), compile-time indexed.
// ---------------------------------------------------------------------------
#define OFF_T   ((size_t)0)                                   // 3 * 8192*64
#define OFF_H   (OFF_T  + (size_t)3 * MROWS * RR)
#define OFF_Q   (OFF_H  + (size_t)MROWS * DMODEL)
#define OFF_K   (OFF_Q  + (size_t)MROWS * DMODEL)
#define OFF_V   (OFF_K  + (size_t)MROWS * DMODEL)
#define OFF_O   (OFF_V  + (size_t)MROWS * DMODEL)
#define OFF_O2  (OFF_O  + (size_t)MROWS * DMODEL)
#define OFF_SC  (OFF_O2 + (size_t)MROWS * DMODEL)             // 512 MB scores
#define OFF_PS  (OFF_SC + (size_t)BSZ * HH * NSEQ * NSEQ)
#define OFF_PQ  (OFF_PS + (size_t)64 * DMODEL)
#define OFF_ST  (OFF_PQ + (size_t)64 * DMODEL)
#define ARENA_TOTAL (OFF_ST + (size_t)2 * DMODEL)

__device__ float g_arena[ARENA_TOTAL];

// ---------------------------------------------------------------------------
// Shared GEMM body: C[M,N] = A[M,K] @ B[K,N] (+ bias[N])
// ---------------------------------------------------------------------------
__device__ __forceinline__ void gemm_body(const float* __restrict__ A,
                                          const float* __restrict__ Bm,
                                          const float* __restrict__ bias,
                                          float* __restrict__ C,
                                          int Nn, int K) {
    __shared__ float As[16][65];
    __shared__ float Bs[16][65];
    int tid = threadIdx.x;
    int tx = tid & 15, ty = tid >> 4;
    int m0 = blockIdx.y * 64, n0 = blockIdx.x * 64;
    float acc[4][4] = {};

    for (int k0 = 0; k0 < K; k0 += 16) {
#pragma unroll
        for (int r = 0; r < 4; r++) {
            int idx = tid + r * 256;
            int m = idx >> 4;
            int kk = idx & 15;
            As[kk][m] = A[(size_t)(m0 + m) * K + k0 + kk];
        }
#pragma unroll
        for (int r = 0; r < 4; r++) {
            int idx = tid + r * 256;
            int kk = idx >> 6;
            int nn = idx & 63;
            Bs[kk][nn] = Bm[(size_t)(k0 + kk) * Nn + n0 + nn];
        }
        __syncthreads();
#pragma unroll
        for (int kk = 0; kk < 16; kk++) {
            float a4[4], b4[4];
#pragma unroll
            for (int i = 0; i < 4; i++) a4[i] = As[kk][ty * 4 + i];
#pragma unroll
            for (int j = 0; j < 4; j++) b4[j] = Bs[kk][tx * 4 + j];
#pragma unroll
            for (int i = 0; i < 4; i++)
#pragma unroll
                for (int j = 0; j < 4; j++)
                    acc[i][j] += a4[i] * b4[j];
        }
        __syncthreads();
    }
#pragma unroll
    for (int i = 0; i < 4; i++) {
        int m = m0 + ty * 4 + i;
#pragma unroll
        for (int j = 0; j < 4; j++) {
            int n = n0 + tx * 4 + j;
            float v = acc[i][j];
            if (bias) v += bias[n];
            C[(size_t)m * Nn + n] = v;
        }
    }
}

__global__ void sgemm_kernel(const float* __restrict__ Aext, size_t aOff,
                             const float* __restrict__ Bm,
                             const float* __restrict__ bias,
                             size_t cOff, int Nn, int K) {
    const float* A = Aext ? Aext : (g_arena + aOff);
    gemm_body(A, Bm, bias, g_arena + cOff, Nn, K);
}

__global__ void sgemm3_kernel(size_t aOff, size_t aStride,
                              const float* __restrict__ B0,
                              const float* __restrict__ B1,
                              const float* __restrict__ B2,
                              size_t cOff, size_t cStride, int Nn, int K) {
    int z = blockIdx.z;
    const float* Bm = (z == 0) ? B0 : (z == 1) ? B1 : B2;
    gemm_body(g_arena + aOff + (size_t)z * aStride, Bm, nullptr,
              g_arena + cOff + (size_t)z * cStride, Nn, K);
}

// ---------------------------------------------------------------------------
// QK^T scores per (b,h): S[bh][i][j] = (q_i . k_j) / sqrt(32)
// 64x64 tile, 4x4 per thread, but SMEM transposed [d][row] so the inner
// loop is 2x LDS.128 + 16 FMA (89% issue efficiency vs 67% scalar).
// ---------------------------------------------------------------------------
__global__ void qk_kernel() {
    const float* q = g_arena + OFF_Q;
    const float* k = g_arena + OFF_K;
    float* S = g_arena + OFF_SC;
    int bh = blockIdx.z;
    int h = bh & (HH - 1), b = bh >> 3;
    int i0 = blockIdx.y * 64, j0 = blockIdx.x * 64;
    __shared__ __align__(16) float Qt[DHD][68];   // [d][row], pad 68
    __shared__ __align__(16) float Kt[DHD][68];
    int tid = threadIdx.x;
    int d = tid & 31, r0 = tid >> 5;
    const float* qb = q + ((size_t)b * NSEQ) * DMODEL + h * DHD;
    const float* kb = k + ((size_t)b * NSEQ) * DMODEL + h * DHD;
#pragma unroll
    for (int r = r0; r < 64; r += 8) {
        Qt[d][r] = qb[(size_t)(i0 + r) * DMODEL + d];
        Kt[d][r] = kb[(size_t)(j0 + r) * DMODEL + d];
    }
    __syncthreads();
    int tx = tid & 15, ty = tid >> 4;
    float acc[4][4] = {};
#pragma unroll
    for (int dd = 0; dd < DHD; dd++) {
        float4 a4 = *reinterpret_cast<const float4*>(&Qt[dd][ty * 4]);
        float4 b4 = *reinterpret_cast<const float4*>(&Kt[dd][tx * 4]);
        float aa[4] = {a4.x, a4.y, a4.z, a4.w};
        float bb[4] = {b4.x, b4.y, b4.z, b4.w};
#pragma unroll
        for (int i = 0; i < 4; i++)
#pragma unroll
            for (int j = 0; j < 4; j++)
                acc[i][j] += aa[i] * bb[j];
    }
    const float scale = 1.0f / sqrtf((float)DHD);
    float* Sp = S + ((size_t)bh * NSEQ + i0) * NSEQ + j0;
#pragma unroll
    for (int i = 0; i < 4; i++) {
        float4 v4 = make_float4(acc[i][0] * scale, acc[i][1] * scale,
                                acc[i][2] * scale, acc[i][3] * scale);
        *reinterpret_cast<float4*>(Sp + (size_t)(ty * 4 + i) * NSEQ + tx * 4) = v4;
    }
}

// ---------------------------------------------------------------------------
// Fused per-row top-32 + softmax + sparse PV.
// Statistical prefilter (tau from row max/mean) shrinks the exact radix
// select to ~32-400 candidates. Exactness: cnt(>=tau) >= 32 implies
// thr >= tau, so every kept element is a candidate.
// __launch_bounds__(256, 6): cap registers so >= 6 blocks/SM stay resident
// through the sync-heavy select phases.
// ---------------------------------------------------------------------------
__device__ __forceinline__ unsigned fkey(float f) {
    unsigned u = __float_as_uint(f);
    return u ^ (((int)u < 0) ? 0xFFFFFFFFu : 0x80000000u);
}

// Block reduces with trailing sync (safe for back-to-back use).
__device__ __forceinline__ float blkReduceMax(float v, float* red) {
#pragma unroll
    for (int o = 16; o; o >>= 1) v = fmaxf(v, __shfl_xor_sync(0xffffffffu, v, o));
    if ((threadIdx.x & 31) == 0) red[threadIdx.x >> 5] = v;
    __syncthreads();
    float m = red[0];
#pragma unroll
    for (int i = 1; i < 8; i++) m = fmaxf(m, red[i]);
    __syncthreads();
    return m;
}

__device__ __forceinline__ float blkReduceSum(float v, float* red) {
#pragma unroll
    for (int o = 16; o; o >>= 1) v += __shfl_xor_sync(0xffffffffu, v, o);
    if ((threadIdx.x & 31) == 0) red[threadIdx.x >> 5] = v;
    __syncthreads();
    float m = red[0];
#pragma unroll
    for (int i = 1; i < 8; i++) m += red[i];
    __syncthreads();
    return m;
}

__device__ __forceinline__ unsigned blkReduceSumU(unsigned v, unsigned* wr) {
#pragma unroll
    for (int o = 16; o; o >>= 1) v += __shfl_xor_sync(0xffffffffu, v, o);
    if ((threadIdx.x & 31) == 0) wr[threadIdx.x >> 5] = v;
    __syncthreads();
    unsigned s = 0;
#pragma unroll
    for (int i = 0; i < 8; i++) s += wr[i];
    __syncthreads();
    return s;
}

__global__ void __launch_bounds__(256, 6) attn_row_kernel() {
    const float* S = g_arena + OFF_SC;
    const float* v = g_arena + OFF_V;
    float* o = g_arena + OFF_O;

    __shared__ unsigned hist[256];
    __shared__ unsigned wsum[8];
    __shared__ int sel_idx[NSEQ];
    __shared__ float sel_p[NSEQ];
    __shared__ float red[8];
    __shared__ float part[256];
    __shared__ unsigned sh_pref, sh_k, sh_done;

    int row = blockIdx.x;
    int n = row & (NSEQ - 1);
    int bh = row >> 11;
    int h = bh & (HH - 1), b = bh >> 3;
    int t = threadIdx.x;
    int lane = t & 31, w = t >> 5;

    const float4* srow4 = reinterpret_cast<const float4*>(
        S + ((size_t)bh * NSEQ + n) * NSEQ);

    // Thread t owns indices 8t..8t+7 (two streaming float4 loads).
    float val8[8];
    float4 va = __ldcs(srow4 + 2 * t);
    float4 vb = __ldcs(srow4 + 2 * t + 1);
    val8[0] = va.x; val8[1] = va.y; val8[2] = va.z; val8[3] = va.w;
    val8[4] = vb.x; val8[5] = vb.y; val8[6] = vb.z; val8[7] = vb.w;
    float mloc = -INFINITY, sloc = 0.f;
#pragma unroll
    for (int r = 0; r < 8; r++) {
        mloc = fmaxf(mloc, val8[r]);
        sloc += val8[r];
    }
    float m = blkReduceMax(mloc, red);
    float mu = blkReduceSum(sloc, red) * (1.0f / (float)NSEQ);

    // Threshold search: start at (m+mu)/2 (~= the top-32 boundary for
    // near-Gaussian rows); halve toward mu until >= 32 candidates.
    // Deterministic fallback to -inf after 4 failed tries.
    float tau = 0.5f * (m + mu);
    unsigned cnt = 0;
#pragma unroll 1
    for (int it = 0; it < 5; it++) {
        unsigned lc = 0;
#pragma unroll
        for (int r = 0; r < 8; r++) lc += (val8[r] >= tau) ? 1u : 0u;
        cnt = blkReduceSumU(lc, wsum);
        if (cnt >= KSP) break;
        tau = (it >= 3) ? -INFINITY : 0.5f * (tau + mu);
    }

    // Compact candidates (val >= tau), deterministic rank by (t, r).
    unsigned pass8 = 0u, cnt_t = 0u;
#pragma unroll
    for (int r = 0; r < 8; r++)
        if (val8[r] >= tau) { pass8 |= (1u << r); cnt_t++; }
    unsigned pv = cnt_t;
#pragma unroll
    for (int off = 1; off < 32; off <<= 1) {
        unsigned u = __shfl_up_sync(0xffffffffu, pv, off);
        if (lane >= off) pv += u;
    }
    if (lane == 31) wsum[w] = pv;
    if (t == 0) { sh_pref = 0u; sh_k = KSP; sh_done = 0u; }
    __syncthreads();
    unsigned addp = 0u, c_all = 0u;
#pragma unroll
    for (int w2 = 0; w2 < 8; w2++) {
        unsigned ws = wsum[w2];
        if (w2 < w) addp += ws;
        c_all += ws;
    }
    int pos = (int)(pv + addp - cnt_t);
    int c = (int)c_all;                 // >= 32 guaranteed
#pragma unroll
    for (int r = 0; r < 8; r++)
        if (pass8 & (1u << r)) {
            sel_idx[pos] = 8 * t + r;
            sel_p[pos] = val8[r];
            pos++;
        }
    __syncthreads();

    // Exact radix select of the 32nd-largest among the c candidates (ties
    // counted — matches jax.lax.top_k's k-th sorted value under >=).
    // Early exit when the selected bucket is entirely kept (suf == kneed).
#pragma unroll 1
    for (int shift = 24; shift >= 0; shift -= 8) {
        if (sh_done) break;
        hist[t] = 0u;
        unsigned pref = sh_pref;
        unsigned kneed = sh_k;
        __syncthreads();
        unsigned mask = (shift == 24) ? 0u : (0xFFFFFFFFu << (shift + 8));
        for (int e = t; e < c; e += 256) {
            unsigned key = fkey(sel_p[e]);
            if ((key & mask) == pref)
                atomicAdd(&hist[(key >> shift) & 255u], 1u);
        }
        __syncthreads();
        unsigned own = hist[t];
        unsigned sv = own;
#pragma unroll
        for (int off = 1; off < 32; off <<= 1) {
            unsigned u = __shfl_down_sync(0xffffffffu, sv, off);
            if (lane + off < 32) sv += u;
        }
        if (lane == 0) wsum[w] = sv;
        __syncthreads();
        unsigned add = 0u;
#pragma unroll
        for (int w2 = 0; w2 < 8; w2++)
            if (w2 > w) add += wsum[w2];
        unsigned suf = sv + add;
        if (suf >= kneed && (suf - own) < kneed) {
            sh_pref = pref | ((unsigned)t << shift);
            sh_k = kneed - (suf - own);
            if (suf == kneed) sh_done = 1u;
        }
        __syncthreads();
    }
    unsigned thr = sh_pref;

    // Final in-place compaction of kept entries (fkey >= thr) among the
    // candidates. Reads complete before the scan's sync; writes after.
    float kv[8];
    int ki[8];
    unsigned keep8 = 0u, kc = 0u;
#pragma unroll
    for (int i = 0; i < 8; i++) {
        int e = t + 256 * i;
        if (e < c) {
            float x = sel_p[e];
            kv[i] = x;
            ki[i] = sel_idx[e];
            if (fkey(x) >= thr) { keep8 |= (1u << i); kc++; }
        }
    }
    unsigned pv2 = kc;
#pragma unroll
    for (int off = 1; off < 32; off <<= 1) {
        unsigned u = __shfl_up_sync(0xffffffffu, pv2, off);
        if (lane >= off) pv2 += u;
    }
    if (lane == 31) wsum[w] = pv2;
    __syncthreads();
    unsigned addp2 = 0u, c2_all = 0u;
#pragma unroll
    for (int w2 = 0; w2 < 8; w2++) {
        unsigned ws = wsum[w2];
        if (w2 < w) addp2 += ws;
        c2_all += ws;
    }
    int pos2 = (int)(pv2 + addp2 - kc);
    int c2 = (int)c2_all;
#pragma unroll
    for (int i = 0; i < 8; i++)
        if (keep8 & (1u << i)) {
            sel_idx[pos2] = ki[i];
            sel_p[pos2] = kv[i];
            pos2++;
        }
    __syncthreads();

    // Sparse exp + sum over the kept set (~32 entries).
    float loc = 0.f;
    for (int e = t; e < c2; e += 256) {
        float p = __expf(sel_p[e] - m);
        sel_p[e] = p;
        loc += p;
    }
    float tot = blkReduceSum(loc, red);   // its sync publishes sel_p
    float inv = 1.f / tot;

    // Sparse P @ V: warp w handles entries e ≡ w (mod 8); lane gathers
    // V[sel_idx[e]][h*32+lane] — one coalesced 128B row per entry.
    const float* vbp = v + ((size_t)b * NSEQ) * DMODEL + h * DHD + lane;
    float acc = 0.f;
    for (int e = w; e < c2; e += 8)
        acc += sel_p[e] * vbp[(size_t)sel_idx[e] * DMODEL];
    part[t] = acc;
    __syncthreads();
    if (t < 32) {
        float r = part[t];
#pragma unroll
        for (int ww = 1; ww < 8; ww++) r += part[ww * 32 + t];
        o[((size_t)b * NSEQ + n) * DMODEL + h * DHD + t] = r * inv;
    }
}

// ---------------------------------------------------------------------------
// BatchNorm over (B,N) per channel — deterministic two-stage reduction.
// ---------------------------------------------------------------------------
__global__ void bn_partial_kernel() {
    const float* X = g_arena + OFF_H;
    float* ps = g_arena + OFF_PS;
    float* pq = g_arena + OFF_PQ;
    int blk = blockIdx.x;
    int t = threadIdx.x;
    float s = 0.f, q = 0.f;
    for (int r = 0; r < 128; r++) {
        float val = X[(size_t)(blk * 128 + r) * DMODEL + t];
        s += val;
        q += val * val;
    }
    ps[blk * DMODEL + t] = s;
    pq[blk * DMODEL + t] = q;
}

__global__ void bn_finalize_kernel() {
    const float* ps = g_arena + OFF_PS;
    const float* pq = g_arena + OFF_PQ;
    float* stat = g_arena + OFF_ST;
    int t = threadIdx.x;
    float s = 0.f, q = 0.f;
    for (int b = 0; b < 64; b++) {
        s += ps[b * DMODEL + t];
        q += pq[b * DMODEL + t];
    }
    float mu = s * (1.0f / (float)MROWS);
    float var = q * (1.0f / (float)MROWS) - mu * mu;
    stat[t] = mu;
    stat[DMODEL + t] = rsqrtf(var + 1e-5f);
}

__global__ void bn_apply_kernel(const float* __restrict__ gamma,
                                const float* __restrict__ beta,
                                float* __restrict__ out) {
    const float* X = g_arena + OFF_H;
    const float* stat = g_arena + OFF_ST;
    size_t idx = (size_t)blockIdx.x * 256 + threadIdx.x;
    int c = (int)(idx & (DMODEL - 1));
    out[idx] = (X[idx] - stat[c]) * stat[DMODEL + c] * gamma[c] + beta[c];
}

// ---------------------------------------------------------------------------
// Launch — kernel launches ONLY (graph-capture safe)
// ---------------------------------------------------------------------------
extern "C" void kernel_launch(void* const* d_in, const int* in_sizes, int n_in,
                              void* d_out, int out_size) {
    const float* x    = (const float*)d_in[0];
    const float* U_np = (const float*)d_in[1];
    const float* V_np = (const float*)d_in[2];
    const float* b_np = (const float*)d_in[3];
    const float* U_q  = (const float*)d_in[4];
    const float* V_q  = (const float*)d_in[5];
    const float* U_k  = (const float*)d_in[6];
    const float* V_k  = (const float*)d_in[7];
    const float* U_v  = (const float*)d_in[8];
    const float* V_v  = (const float*)d_in[9];
    const float* U_o  = (const float*)d_in[10];
    const float* V_o  = (const float*)d_in[11];
    const float* b_o  = (const float*)d_in[12];
    const float* U_op = (const float*)d_in[13];
    const float* V_op = (const float*)d_in[14];
    const float* b_op = (const float*)d_in[15];
    const float* gamma = (const float*)d_in[16];
    const float* beta  = (const float*)d_in[17];
    float* out = (float*)d_out;

    dim3 gN1(1, MROWS / 64);        // Nn = 64
    dim3 gN4(4, MROWS / 64);        // Nn = 256
    dim3 gN1z(1, MROWS / 64, 3);    // batched QKV stage-1
    dim3 gN4z(4, MROWS / 64, 3);    // batched QKV stage-2

    // h = (x @ U_np) @ V_np + b_np
    sgemm_kernel<<<gN1, 256>>>(x, 0, U_np, nullptr, OFF_T, RR, DMODEL);
    sgemm_kernel<<<gN4, 256>>>(nullptr, OFF_T, V_np, b_np, OFF_H, DMODEL, RR);
    // q,k,v batched
    sgemm3_kernel<<<gN1z, 256>>>(OFF_H, 0, U_q, U_k, U_v,
                                 OFF_T, (size_t)MROWS * RR, RR, DMODEL);
    sgemm3_kernel<<<gN4z, 256>>>(OFF_T, (size_t)MROWS * RR, V_q, V_k, V_v,
                                 OFF_Q, (size_t)MROWS * DMODEL, DMODEL, RR);

    // scores (64x64 tiles, float4 smem inner loop)
    qk_kernel<<<dim3(NSEQ / 64, NSEQ / 64, BSZ * HH), 256>>>();
    // top-k + softmax + sparse PV
    attn_row_kernel<<<BSZ * HH * NSEQ, 256>>>();

    // attention out proj + out_proj
    sgemm_kernel<<<gN1, 256>>>(nullptr, OFF_O, U_o, nullptr, OFF_T, RR, DMODEL);
    sgemm_kernel<<<gN4, 256>>>(nullptr, OFF_T, V_o, b_o, OFF_O2, DMODEL, RR);
    sgemm_kernel<<<gN1, 256>>>(nullptr, OFF_O2, U_op, nullptr, OFF_T, RR, DMODEL);
    sgemm_kernel<<<gN4, 256>>>(nullptr, OFF_T, V_op, b_op, OFF_H, DMODEL, RR);

    // BatchNorm
    bn_partial_kernel<<<64, 256>>>();
    bn_finalize_kernel<<<1, 256>>>();
    bn_apply_kernel<<<(MROWS * DMODEL) / 256, 256>>>(gamma, beta, out);
}